// round 1
// baseline (speedup 1.0000x reference)
#include <cuda_runtime.h>

#define NN 100000
#define EE 1600000
#define ETOT (EE + NN)
#define GG 64
#define HH 4
#define CC 64
#define NF 32
#define DF 16
#define OO 32
#define HC (HH * CC)

// ---------------- device scratch (static, allocation-free) ----------------
__device__ __align__(16) float    g_h[NN * CC];          // 25.6 MB
__device__ __align__(16) float    g_xh[NN * HC];         // 102.4 MB
__device__ __align__(16) float    g_agg[NN * HC];        // 102.4 MB
__device__ __align__(16) float    g_as[NN * HH];
__device__ __align__(16) float    g_ad[NN * HH];
__device__ __align__(16) unsigned g_menc[NN * HH];
__device__ __align__(16) float    g_m[NN * HH];
__device__ __align__(16) float    g_s[NN * HH];
__device__ __align__(16) float    g_r[NN * HH];
__device__ __align__(16) float    g_dpre[GG * CC];
__device__ __align__(16) float    g_vas[HH * CC];
__device__ __align__(16) float    g_vad[HH * CC];

// ---------------- helpers ----------------
__device__ __forceinline__ float lrelu(float v) { return v > 0.f ? v : 0.2f * v; }

__device__ __forceinline__ unsigned enc_f(float v) {
    unsigned b = __float_as_uint(v);
    return (b & 0x80000000u) ? ~b : (b | 0x80000000u);
}
__device__ __forceinline__ float dec_f(unsigned u) {
    unsigned b = (u & 0x80000000u) ? (u ^ 0x80000000u) : ~u;
    return __uint_as_float(b);
}

__device__ __forceinline__ void red_add_v4(float4* p, float4 v) {
    asm volatile("red.global.add.v4.f32 [%0], {%1, %2, %3, %4};"
                 :: "l"(p), "f"(v.x), "f"(v.y), "f"(v.z), "f"(v.w)
                 : "memory");
}

// ---------------- kernels ----------------
// dpre[g,c] = drone_feat[g]·drone_W[c] + drone_b[c]
__global__ void k_dpre(const float* __restrict__ df, const float* __restrict__ dW,
                       const float* __restrict__ db) {
    int idx = blockIdx.x * blockDim.x + threadIdx.x;
    if (idx >= GG * CC) return;
    int g = idx / CC, c = idx % CC;
    const float4* a = (const float4*)(df + g * DF);
    const float4* w = (const float4*)(dW + c * DF);
    float acc = db[c];
#pragma unroll
    for (int i = 0; i < DF / 4; i++) {
        float4 av = a[i], wv = w[i];
        acc += av.x * wv.x + av.y * wv.y + av.z * wv.z + av.w * wv.w;
    }
    g_dpre[idx] = acc;
}

// h[n,c] = x[n]·node_W[c] + node_b[c] + dpre[batch[n],c]
__global__ void k_hinit(const float* __restrict__ x, const int* __restrict__ batch,
                        const float* __restrict__ nW, const float* __restrict__ nb) {
    int idx = blockIdx.x * blockDim.x + threadIdx.x;
    if (idx >= NN * CC) return;
    int n = idx >> 6, c = idx & 63;
    float acc = nb[c] + g_dpre[batch[n] * CC + c];
    const float4* xr = (const float4*)(x + n * NF);
    const float4* wr = (const float4*)(nW + c * NF);
#pragma unroll
    for (int i = 0; i < NF / 4; i++) {
        float4 av = xr[i], wv = wr[i];
        acc += av.x * wv.x + av.y * wv.y + av.z * wv.z + av.w * wv.w;
    }
    g_h[idx] = acc;
}

// va_{s,d}[h,c'] = sum_c a[h,c] * W[h*64+c, c']  (fold attention vectors thru W)
__global__ void k_va(const float* __restrict__ W, const float* __restrict__ asrc,
                     const float* __restrict__ adst) {
    int t = threadIdx.x;            // 512 threads, one block
    int which = t >> 8;             // 0 -> src, 1 -> dst
    int j = t & 255;
    int h = j >> 6, cp = j & 63;
    const float* a = which ? adst : asrc;
    float acc = 0.f;
#pragma unroll 4
    for (int c = 0; c < CC; c++)
        acc += a[h * CC + c] * W[(h * CC + c) * CC + cp];
    (which ? g_vad : g_vas)[j] = acc;
}

// alpha_{s,d}[n,h] = h[n]·va_{s,d}[h]
__global__ void k_alpha() {
    int idx = blockIdx.x * blockDim.x + threadIdx.x;
    if (idx >= NN * HH) return;
    int n = idx >> 2, h = idx & 3;
    const float4* hr = (const float4*)(g_h + n * CC);
    const float4* vs = (const float4*)(g_vas + h * CC);
    const float4* vd = (const float4*)(g_vad + h * CC);
    float s = 0.f, d = 0.f;
#pragma unroll
    for (int i = 0; i < CC / 4; i++) {
        float4 hv = hr[i], sv = vs[i], dv = vd[i];
        s += hv.x * sv.x + hv.y * sv.y + hv.z * sv.z + hv.w * sv.w;
        d += hv.x * dv.x + hv.y * dv.y + hv.z * dv.z + hv.w * dv.w;
    }
    g_as[idx] = s;
    g_ad[idx] = d;
}

// zero agg / menc / s
__global__ void k_zero() {
    int idx = blockIdx.x * blockDim.x + threadIdx.x;
    if (idx < NN * HC / 4) ((float4*)g_agg)[idx] = make_float4(0.f, 0.f, 0.f, 0.f);
    if (idx < NN * HH) { g_menc[idx] = 0u; g_s[idx] = 0.f; }
}

// xh[n, h*64+c] = sum_{c'} h[n,c'] * W[h*64+c, c']
// block: 256 threads, 32 nodes; W transposed in SMEM with pad-257 rows.
#define TNODES 32
#define SMEM_T ((64 * 257 + TNODES * 64) * 4)
__global__ void k_transform(const float* __restrict__ W) {
    extern __shared__ float sm[];
    float* Wt = sm;                  // [64][257]
    float* hs = sm + 64 * 257;       // [32][64]
    for (int idx = threadIdx.x; idx < 256 * 64; idx += 256) {
        int j = idx >> 6, c = idx & 63;
        Wt[c * 257 + j] = W[idx];
    }
    int base = blockIdx.x * TNODES;
    for (int idx = threadIdx.x; idx < TNODES * 64; idx += 256)
        hs[idx] = g_h[base * 64 + idx];   // N divisible by 32 -> no OOB
    __syncthreads();

    int jj = threadIdx.x & 63;
    int grp = threadIdx.x >> 6;          // 0..3, nodes grp*8 .. grp*8+7
    float acc[4][8];
#pragma unroll
    for (int k = 0; k < 4; k++)
#pragma unroll
        for (int nd = 0; nd < 8; nd++) acc[k][nd] = 0.f;

#pragma unroll 4
    for (int c = 0; c < 64; c++) {
        float w0 = Wt[c * 257 + jj];
        float w1 = Wt[c * 257 + jj + 64];
        float w2 = Wt[c * 257 + jj + 128];
        float w3 = Wt[c * 257 + jj + 192];
        const float* hrow = &hs[grp * 8 * 64 + c];
#pragma unroll
        for (int nd = 0; nd < 8; nd++) {
            float hv = hrow[nd * 64];
            acc[0][nd] += w0 * hv;
            acc[1][nd] += w1 * hv;
            acc[2][nd] += w2 * hv;
            acc[3][nd] += w3 * hv;
        }
    }
#pragma unroll
    for (int nd = 0; nd < 8; nd++) {
        int n = base + grp * 8 + nd;
        float* xr = g_xh + n * 256;
#pragma unroll
        for (int k = 0; k < 4; k++) xr[k * 64 + jj] = acc[k][nd];
    }
}

// segment max via order-preserving uint atomicMax
__global__ void k_max(const int* __restrict__ src, const int* __restrict__ dst) {
    int e = blockIdx.x * blockDim.x + threadIdx.x;
    if (e >= ETOT) return;
    int s, d;
    if (e < EE) { s = src[e]; d = dst[e]; } else { s = e - EE; d = s; }
    float4 a4 = *(const float4*)(g_as + s * 4);
    float4 b4 = *(const float4*)(g_ad + d * 4);
    float v0 = lrelu(a4.x + b4.x), v1 = lrelu(a4.y + b4.y);
    float v2 = lrelu(a4.z + b4.z), v3 = lrelu(a4.w + b4.w);
    unsigned* mp = g_menc + d * 4;
    atomicMax(mp + 0, enc_f(v0));
    atomicMax(mp + 1, enc_f(v1));
    atomicMax(mp + 2, enc_f(v2));
    atomicMax(mp + 3, enc_f(v3));
}

__global__ void k_decode() {
    int idx = blockIdx.x * blockDim.x + threadIdx.x;
    if (idx >= NN * HH) return;
    g_m[idx] = dec_f(g_menc[idx]);
}

__global__ void k_sum(const int* __restrict__ src, const int* __restrict__ dst) {
    int e = blockIdx.x * blockDim.x + threadIdx.x;
    if (e >= ETOT) return;
    int s, d;
    if (e < EE) { s = src[e]; d = dst[e]; } else { s = e - EE; d = s; }
    float4 a4 = *(const float4*)(g_as + s * 4);
    float4 b4 = *(const float4*)(g_ad + d * 4);
    float4 m4 = *(const float4*)(g_m + d * 4);
    float* sp = g_s + d * 4;
    atomicAdd(sp + 0, __expf(lrelu(a4.x + b4.x) - m4.x));
    atomicAdd(sp + 1, __expf(lrelu(a4.y + b4.y) - m4.y));
    atomicAdd(sp + 2, __expf(lrelu(a4.z + b4.z) - m4.z));
    atomicAdd(sp + 3, __expf(lrelu(a4.w + b4.w) - m4.w));
}

__global__ void k_recip() {
    int idx = blockIdx.x * blockDim.x + threadIdx.x;
    if (idx >= NN * HH) return;
    g_r[idx] = 1.0f / (g_s[idx] + 1e-16f);
}

// one warp per edge: agg[dst] += alpha * xh[src]   (red.global.add.v4.f32)
__global__ void k_agg(const int* __restrict__ src, const int* __restrict__ dst) {
    int gw = (blockIdx.x * blockDim.x + threadIdx.x) >> 5;
    int lane = threadIdx.x & 31;
    if (gw >= ETOT) return;
    int s, d;
    if (gw < EE) { s = src[gw]; d = dst[gw]; } else { s = gw - EE; d = s; }
    float4 a4 = *(const float4*)(g_as + s * 4);
    float4 b4 = *(const float4*)(g_ad + d * 4);
    float4 m4 = *(const float4*)(g_m + d * 4);
    float4 r4 = *(const float4*)(g_r + d * 4);
    float al[4];
    al[0] = __expf(lrelu(a4.x + b4.x) - m4.x) * r4.x;
    al[1] = __expf(lrelu(a4.y + b4.y) - m4.y) * r4.y;
    al[2] = __expf(lrelu(a4.z + b4.z) - m4.z) * r4.z;
    al[3] = __expf(lrelu(a4.w + b4.w) - m4.w) * r4.w;

    const float4* xr = (const float4*)(g_xh + (long)s * 256);
    float4* orow = (float4*)(g_agg + (long)d * 256);
    float a0 = al[lane >> 4];
    float a1 = al[2 + (lane >> 4)];
    float4 v0 = xr[lane];
    v0.x *= a0; v0.y *= a0; v0.z *= a0; v0.w *= a0;
    red_add_v4(orow + lane, v0);
    float4 v1 = xr[lane + 32];
    v1.x *= a1; v1.y *= a1; v1.z *= a1; v1.w *= a1;
    red_add_v4(orow + lane + 32, v1);
}

// head mean + bias + LayerNorm + ReLU + residual into h. 4 nodes / 256-thr block.
__global__ void k_epi(const float* __restrict__ cb, const float* __restrict__ lg,
                      const float* __restrict__ lb) {
    int idx = blockIdx.x * 256 + threadIdx.x;   // grid sized exactly N*64/256
    int n = idx >> 6, c = idx & 63;
    const float* ar = g_agg + (long)n * 256;
    float v = 0.25f * (ar[c] + ar[64 + c] + ar[128 + c] + ar[192 + c]) + cb[c];
    float sum = v, sq = v * v;
#pragma unroll
    for (int o = 16; o; o >>= 1) {
        sum += __shfl_xor_sync(0xffffffffu, sum, o);
        sq  += __shfl_xor_sync(0xffffffffu, sq, o);
    }
    __shared__ float ws[8], wq[8];
    int w = threadIdx.x >> 5;
    if ((threadIdx.x & 31) == 0) { ws[w] = sum; wq[w] = sq; }
    __syncthreads();
    int nl = threadIdx.x >> 6;
    float tsum = ws[nl * 2] + ws[nl * 2 + 1];
    float tsq  = wq[nl * 2] + wq[nl * 2 + 1];
    float mu = tsum * (1.f / 64.f);
    float var = tsq * (1.f / 64.f) - mu * mu;
    float y = (v - mu) * rsqrtf(var + 1e-5f) * lg[c] + lb[c];
    g_h[n * 64 + c] += fmaxf(y, 0.f);
}

// out[n,o] = h[n]·out_W[o] + out_b[o]
__global__ void k_out(const float* __restrict__ oW, const float* __restrict__ ob,
                      float* __restrict__ out) {
    int idx = blockIdx.x * blockDim.x + threadIdx.x;
    if (idx >= NN * OO) return;
    int n = idx >> 5, o = idx & 31;
    const float4* hr = (const float4*)(g_h + n * 64);
    const float4* wr = (const float4*)(oW + o * 64);
    float acc = ob[o];
#pragma unroll
    for (int i = 0; i < 16; i++) {
        float4 hv = hr[i], wv = wr[i];
        acc += hv.x * wv.x + hv.y * wv.y + hv.z * wv.z + hv.w * wv.w;
    }
    out[idx] = acc;
}

// ---------------- launch ----------------
extern "C" void kernel_launch(void* const* d_in, const int* in_sizes, int n_in,
                              void* d_out, int out_size) {
    const float* x = (const float*)d_in[0];
    const int* eidx;
    const float* dfeat;
    // disambiguate dict-order vs signature-order: drone_feat is 1024 elems,
    // edge_index is 3.2M elems
    if (in_sizes[1] == GG * DF) { dfeat = (const float*)d_in[1]; eidx = (const int*)d_in[2]; }
    else                        { eidx = (const int*)d_in[1];    dfeat = (const float*)d_in[2]; }
    const int*   batch = (const int*)d_in[3];
    const float* nW = (const float*)d_in[4];
    const float* nb = (const float*)d_in[5];
    const float* dW = (const float*)d_in[6];
    const float* db = (const float*)d_in[7];
    const float* oW = (const float*)d_in[20];
    const float* ob = (const float*)d_in[21];
    const int* srcA = eidx;
    const int* dstA = eidx + EE;

    cudaFuncSetAttribute(k_transform, cudaFuncAttributeMaxDynamicSharedMemorySize, SMEM_T);

    k_dpre<<<(GG * CC + 255) / 256, 256>>>(dfeat, dW, db);
    k_hinit<<<(NN * CC) / 256, 256>>>(x, batch, nW, nb);

    for (int l = 0; l < 2; l++) {
        int b = 8 + l * 6;
        const float* W  = (const float*)d_in[b];
        const float* as = (const float*)d_in[b + 1];
        const float* ad = (const float*)d_in[b + 2];
        const float* cb = (const float*)d_in[b + 3];
        const float* lg = (const float*)d_in[b + 4];
        const float* lb = (const float*)d_in[b + 5];

        k_zero<<<(NN * HC / 4 + 255) / 256, 256>>>();
        k_va<<<1, 512>>>(W, as, ad);
        k_alpha<<<(NN * HH + 255) / 256, 256>>>();
        k_transform<<<NN / TNODES, 256, SMEM_T>>>(W);
        k_max<<<(ETOT + 255) / 256, 256>>>(srcA, dstA);
        k_decode<<<(NN * HH + 255) / 256, 256>>>();
        k_sum<<<(ETOT + 255) / 256, 256>>>(srcA, dstA);
        k_recip<<<(NN * HH + 255) / 256, 256>>>();
        k_agg<<<(ETOT * 32) / 256, 256>>>(srcA, dstA);
        k_epi<<<(NN * CC) / 256, 256>>>(cb, lg, lb);
    }

    k_out<<<(NN * OO) / 256, 256>>>(oW, ob, (float*)d_out);
}

// round 2
// speedup vs baseline: 2.0490x; 2.0490x over previous
#include <cuda_runtime.h>
#include <cuda_fp16.h>

#define NN 100000
#define EE 1600000
#define ETOT (EE + NN)
#define GG 64
#define HH 4
#define CC 64
#define NF 32
#define DF 16
#define OO 32
#define HC (HH * CC)
#define SB 512
#define NB ((NN + SB - 1) / SB)   // 196

// ---------------- device scratch (static, allocation-free) ----------------
__device__ __align__(16) float  g_h[NN * CC];            // 25.6 MB
__device__ __align__(16) __half g_xh[NN * HC];           // 51.2 MB (fp16)
__device__ __align__(16) float  g_as[NN * HH];
__device__ __align__(16) float  g_ad[NN * HH];
__device__ __align__(16) float  g_ex[ETOT * HH];         // 27.2 MB per-edge exp
__device__ __align__(16) float  g_dpre[GG * CC];
__device__ __align__(16) float  g_vas[HH * CC];
__device__ __align__(16) float  g_vad[HH * CC];
// CSR
__device__ int g_deg[NN];
__device__ int g_pref[NN];
__device__ int g_bsum[NB];
__device__ int g_boff[NB];
__device__ int g_rowstart[NN];
__device__ int g_cur[NN];
__device__ int g_csrc[ETOT];
__device__ int g_cdst[ETOT];

// ---------------- helpers ----------------
__device__ __forceinline__ float lrelu(float v) { return v > 0.f ? v : 0.2f * v; }

// ---------------- init kernels ----------------
__global__ void k_dpre(const float* __restrict__ df, const float* __restrict__ dW,
                       const float* __restrict__ db) {
    int idx = blockIdx.x * blockDim.x + threadIdx.x;
    if (idx >= GG * CC) return;
    int g = idx / CC, c = idx % CC;
    const float4* a = (const float4*)(df + g * DF);
    const float4* w = (const float4*)(dW + c * DF);
    float acc = db[c];
#pragma unroll
    for (int i = 0; i < DF / 4; i++) {
        float4 av = a[i], wv = w[i];
        acc += av.x * wv.x + av.y * wv.y + av.z * wv.z + av.w * wv.w;
    }
    g_dpre[idx] = acc;
}

__global__ void k_hinit(const float* __restrict__ x, const int* __restrict__ batch,
                        const float* __restrict__ nW, const float* __restrict__ nb) {
    int idx = blockIdx.x * blockDim.x + threadIdx.x;
    if (idx >= NN * CC) return;
    int n = idx >> 6, c = idx & 63;
    float acc = nb[c] + g_dpre[batch[n] * CC + c];
    const float4* xr = (const float4*)(x + n * NF);
    const float4* wr = (const float4*)(nW + c * NF);
#pragma unroll
    for (int i = 0; i < NF / 4; i++) {
        float4 av = xr[i], wv = wr[i];
        acc += av.x * wv.x + av.y * wv.y + av.z * wv.z + av.w * wv.w;
    }
    g_h[idx] = acc;
}

// ---------------- CSR build (once per launch) ----------------
__global__ void k_zerodeg() {
    int i = blockIdx.x * blockDim.x + threadIdx.x;
    if (i < NN) g_deg[i] = 0;
}

__global__ void k_hist(const int* __restrict__ dst) {
    int e = blockIdx.x * blockDim.x + threadIdx.x;
    if (e >= ETOT) return;
    int d = (e < EE) ? dst[e] : e - EE;
    atomicAdd(&g_deg[d], 1);
}

__global__ void k_scan1() {
    __shared__ int sm[SB];
    int i = blockIdx.x * SB + threadIdx.x;
    int v = (i < NN) ? g_deg[i] : 0;
    sm[threadIdx.x] = v;
    __syncthreads();
    for (int o = 1; o < SB; o <<= 1) {
        int t = (threadIdx.x >= o) ? sm[threadIdx.x - o] : 0;
        __syncthreads();
        sm[threadIdx.x] += t;
        __syncthreads();
    }
    if (i < NN) g_pref[i] = sm[threadIdx.x];
    if (threadIdx.x == SB - 1) g_bsum[blockIdx.x] = sm[SB - 1];
}

__global__ void k_scan2() {
    __shared__ int sm[256];
    int t = threadIdx.x;
    sm[t] = (t < NB) ? g_bsum[t] : 0;
    __syncthreads();
    for (int o = 1; o < 256; o <<= 1) {
        int v = (t >= o) ? sm[t - o] : 0;
        __syncthreads();
        sm[t] += v;
        __syncthreads();
    }
    if (t < NB) g_boff[t] = (t == 0) ? 0 : sm[t - 1];
}

__global__ void k_scan3() {
    int i = blockIdx.x * blockDim.x + threadIdx.x;
    if (i >= NN) return;
    int start = g_pref[i] - g_deg[i] + g_boff[i / SB];
    g_rowstart[i] = start;
    g_cur[i] = start;
}

__global__ void k_scat(const int* __restrict__ src, const int* __restrict__ dst) {
    int e = blockIdx.x * blockDim.x + threadIdx.x;
    if (e >= ETOT) return;
    int s, d;
    if (e < EE) { s = src[e]; d = dst[e]; } else { s = e - EE; d = s; }
    int pos = atomicAdd(&g_cur[d], 1);
    g_csrc[pos] = s;
    g_cdst[pos] = d;
}

// ---------------- per-layer kernels ----------------
// va_{s,d}[h,c'] = sum_c a[h,c] * W[h*64+c, c']   (8 blocks x 512 thr, 8 thr/output)
__global__ void k_va(const float* __restrict__ W, const float* __restrict__ asrc,
                     const float* __restrict__ adst) {
    int t = blockIdx.x * 512 + threadIdx.x;   // [0, 4096)
    int j = t >> 3;
    int part = t & 7;
    int which = j >> 8;
    int jj = j & 255;
    int h = jj >> 6, cp = jj & 63;
    const float* a = which ? adst : asrc;
    float acc = 0.f;
#pragma unroll
    for (int c = part * 8; c < part * 8 + 8; c++)
        acc += a[h * 64 + c] * W[(h * 64 + c) * 64 + cp];
#pragma unroll
    for (int o = 4; o; o >>= 1) acc += __shfl_xor_sync(0xffffffffu, acc, o);
    if (part == 0) (which ? g_vad : g_vas)[jj] = acc;
}

__global__ void k_alpha() {
    int idx = blockIdx.x * blockDim.x + threadIdx.x;
    if (idx >= NN * HH) return;
    int n = idx >> 2, h = idx & 3;
    const float4* hr = (const float4*)(g_h + n * CC);
    const float4* vs = (const float4*)(g_vas + h * CC);
    const float4* vd = (const float4*)(g_vad + h * CC);
    float s = 0.f, d = 0.f;
#pragma unroll
    for (int i = 0; i < CC / 4; i++) {
        float4 hv = hr[i], sv = vs[i], dv = vd[i];
        s += hv.x * sv.x + hv.y * sv.y + hv.z * sv.z + hv.w * sv.w;
        d += hv.x * dv.x + hv.y * dv.y + hv.z * dv.z + hv.w * dv.w;
    }
    g_as[idx] = s;
    g_ad[idx] = d;
}

// xh[n, h*64+c] = sum_{c'} h[n,c'] * W[h*64+c, c']  -> fp16
#define TNODES 32
#define SMEM_T ((64 * 257 + TNODES * 64) * 4)
__global__ void k_transform(const float* __restrict__ W) {
    extern __shared__ float sm[];
    float* Wt = sm;                  // [64][257]
    float* hs = sm + 64 * 257;       // [32][64]
    for (int idx = threadIdx.x; idx < 256 * 64; idx += 256) {
        int j = idx >> 6, c = idx & 63;
        Wt[c * 257 + j] = W[idx];
    }
    int base = blockIdx.x * TNODES;
    for (int idx = threadIdx.x; idx < TNODES * 64; idx += 256)
        hs[idx] = g_h[base * 64 + idx];
    __syncthreads();

    int jj = threadIdx.x & 63;
    int grp = threadIdx.x >> 6;
    float acc[4][8];
#pragma unroll
    for (int k = 0; k < 4; k++)
#pragma unroll
        for (int nd = 0; nd < 8; nd++) acc[k][nd] = 0.f;

#pragma unroll 4
    for (int c = 0; c < 64; c++) {
        float w0 = Wt[c * 257 + jj];
        float w1 = Wt[c * 257 + jj + 64];
        float w2 = Wt[c * 257 + jj + 128];
        float w3 = Wt[c * 257 + jj + 192];
        const float* hrow = &hs[grp * 8 * 64 + c];
#pragma unroll
        for (int nd = 0; nd < 8; nd++) {
            float hv = hrow[nd * 64];
            acc[0][nd] += w0 * hv;
            acc[1][nd] += w1 * hv;
            acc[2][nd] += w2 * hv;
            acc[3][nd] += w3 * hv;
        }
    }
#pragma unroll
    for (int nd = 0; nd < 8; nd++) {
        int n = base + grp * 8 + nd;
        __half* xr = g_xh + (size_t)n * 256;
#pragma unroll
        for (int k = 0; k < 4; k++) xr[k * 64 + jj] = __float2half(acc[k][nd]);
    }
}

// per-edge exp (no max subtraction; logits are O(10), fp32-safe; softmax shift-invariant)
__global__ void k_ex() {
    int i = blockIdx.x * blockDim.x + threadIdx.x;
    if (i >= ETOT) return;
    int s = g_csrc[i], d = g_cdst[i];
    float4 a4 = *(const float4*)(g_as + s * 4);
    float4 b4 = *(const float4*)(g_ad + d * 4);
    float4 e;
    e.x = __expf(lrelu(a4.x + b4.x));
    e.y = __expf(lrelu(a4.y + b4.y));
    e.z = __expf(lrelu(a4.z + b4.z));
    e.w = __expf(lrelu(a4.w + b4.w));
    *(float4*)(g_ex + i * 4) = e;
}

// fused: gather-aggregate (no atomics) + softmax normalize + head-mean + LN + ReLU + residual
// one warp per destination node; lane l owns head (l>>3), channels ((l&7)*8 .. +7)
__global__ void k_node(const float* __restrict__ cb, const float* __restrict__ lg,
                       const float* __restrict__ lb) {
    int warp = threadIdx.x >> 5, lane = threadIdx.x & 31;
    int n = blockIdx.x * 8 + warp;           // grid exact: NN/8
    int row = g_rowstart[n];
    int deg = g_deg[n];
    int my_h = lane >> 3;
    int cbase = (lane & 7) * 8;

    float acc[8];
#pragma unroll
    for (int k = 0; k < 8; k++) acc[k] = 0.f;
    float4 sum4 = make_float4(0.f, 0.f, 0.f, 0.f);

    for (int base = 0; base < deg; base += 32) {
        int i = base + lane;
        int s_l = 0;
        if (i < deg) {
            s_l = __ldg(g_csrc + row + i);
            float4 e4 = *(const float4*)(g_ex + (size_t)(row + i) * 4);
            sum4.x += e4.x; sum4.y += e4.y; sum4.z += e4.z; sum4.w += e4.w;
        }
        int cnt = min(32, deg - base);
#pragma unroll 2
        for (int k = 0; k < cnt; k++) {
            int s = __shfl_sync(0xffffffffu, s_l, k);
            float a = __ldg(g_ex + (size_t)(row + base + k) * 4 + my_h);
            uint4 raw = __ldg((const uint4*)(g_xh + (size_t)s * 256 + lane * 8));
            __half2 h0 = *reinterpret_cast<__half2*>(&raw.x);
            __half2 h1 = *reinterpret_cast<__half2*>(&raw.y);
            __half2 h2 = *reinterpret_cast<__half2*>(&raw.z);
            __half2 h3 = *reinterpret_cast<__half2*>(&raw.w);
            float2 f0 = __half22float2(h0);
            float2 f1 = __half22float2(h1);
            float2 f2 = __half22float2(h2);
            float2 f3 = __half22float2(h3);
            acc[0] = fmaf(a, f0.x, acc[0]); acc[1] = fmaf(a, f0.y, acc[1]);
            acc[2] = fmaf(a, f1.x, acc[2]); acc[3] = fmaf(a, f1.y, acc[3]);
            acc[4] = fmaf(a, f2.x, acc[4]); acc[5] = fmaf(a, f2.y, acc[5]);
            acc[6] = fmaf(a, f3.x, acc[6]); acc[7] = fmaf(a, f3.y, acc[7]);
        }
    }

    // warp-reduce per-head exp sums
#pragma unroll
    for (int o = 16; o; o >>= 1) {
        sum4.x += __shfl_xor_sync(0xffffffffu, sum4.x, o);
        sum4.y += __shfl_xor_sync(0xffffffffu, sum4.y, o);
        sum4.z += __shfl_xor_sync(0xffffffffu, sum4.z, o);
        sum4.w += __shfl_xor_sync(0xffffffffu, sum4.w, o);
    }
    float sh = (my_h == 0) ? sum4.x : (my_h == 1) ? sum4.y : (my_h == 2) ? sum4.z : sum4.w;
    float rr = 1.0f / (sh + 1e-16f);
#pragma unroll
    for (int k = 0; k < 8; k++) acc[k] *= rr;

    // sum across heads (lanes l, l^8, l^16, l^24 hold heads 0..3 for same channel slice)
#pragma unroll
    for (int k = 0; k < 8; k++) {
        acc[k] += __shfl_xor_sync(0xffffffffu, acc[k], 8);
        acc[k] += __shfl_xor_sync(0xffffffffu, acc[k], 16);
    }

    // head mean + bias, LN stats over the 64 channels (lanes 0..7 within each 8-group)
    float v[8], psum = 0.f, psq = 0.f;
#pragma unroll
    for (int k = 0; k < 8; k++) {
        v[k] = 0.25f * acc[k] + cb[cbase + k];
        psum += v[k];
        psq += v[k] * v[k];
    }
#pragma unroll
    for (int o = 4; o; o >>= 1) {
        psum += __shfl_xor_sync(0xffffffffu, psum, o);
        psq  += __shfl_xor_sync(0xffffffffu, psq, o);
    }
    float mu = psum * (1.f / 64.f);
    float var = psq * (1.f / 64.f) - mu * mu;
    float rs = rsqrtf(var + 1e-5f);

    if (lane < 8) {
        float* hp = g_h + (size_t)n * 64 + cbase;
        float4 o0 = *(float4*)hp;
        float4 o1 = *(float4*)(hp + 4);
        float y;
        y = (v[0] - mu) * rs * lg[cbase + 0] + lb[cbase + 0]; o0.x += fmaxf(y, 0.f);
        y = (v[1] - mu) * rs * lg[cbase + 1] + lb[cbase + 1]; o0.y += fmaxf(y, 0.f);
        y = (v[2] - mu) * rs * lg[cbase + 2] + lb[cbase + 2]; o0.z += fmaxf(y, 0.f);
        y = (v[3] - mu) * rs * lg[cbase + 3] + lb[cbase + 3]; o0.w += fmaxf(y, 0.f);
        y = (v[4] - mu) * rs * lg[cbase + 4] + lb[cbase + 4]; o1.x += fmaxf(y, 0.f);
        y = (v[5] - mu) * rs * lg[cbase + 5] + lb[cbase + 5]; o1.y += fmaxf(y, 0.f);
        y = (v[6] - mu) * rs * lg[cbase + 6] + lb[cbase + 6]; o1.z += fmaxf(y, 0.f);
        y = (v[7] - mu) * rs * lg[cbase + 7] + lb[cbase + 7]; o1.w += fmaxf(y, 0.f);
        *(float4*)hp = o0;
        *(float4*)(hp + 4) = o1;
    }
}

__global__ void k_out(const float* __restrict__ oW, const float* __restrict__ ob,
                      float* __restrict__ out) {
    int idx = blockIdx.x * blockDim.x + threadIdx.x;
    if (idx >= NN * OO) return;
    int n = idx >> 5, o = idx & 31;
    const float4* hr = (const float4*)(g_h + n * 64);
    const float4* wr = (const float4*)(oW + o * 64);
    float acc = ob[o];
#pragma unroll
    for (int i = 0; i < 16; i++) {
        float4 hv = hr[i], wv = wr[i];
        acc += hv.x * wv.x + hv.y * wv.y + hv.z * wv.z + hv.w * wv.w;
    }
    out[idx] = acc;
}

// ---------------- launch ----------------
extern "C" void kernel_launch(void* const* d_in, const int* in_sizes, int n_in,
                              void* d_out, int out_size) {
    const float* x = (const float*)d_in[0];
    const int* eidx;
    const float* dfeat;
    if (in_sizes[1] == GG * DF) { dfeat = (const float*)d_in[1]; eidx = (const int*)d_in[2]; }
    else                        { eidx = (const int*)d_in[1];    dfeat = (const float*)d_in[2]; }
    const int*   batch = (const int*)d_in[3];
    const float* nW = (const float*)d_in[4];
    const float* nb = (const float*)d_in[5];
    const float* dW = (const float*)d_in[6];
    const float* db = (const float*)d_in[7];
    const float* oW = (const float*)d_in[20];
    const float* ob = (const float*)d_in[21];
    const int* srcA = eidx;
    const int* dstA = eidx + EE;

    cudaFuncSetAttribute(k_transform, cudaFuncAttributeMaxDynamicSharedMemorySize, SMEM_T);

    k_dpre<<<(GG * CC + 255) / 256, 256>>>(dfeat, dW, db);
    k_hinit<<<(NN * CC) / 256, 256>>>(x, batch, nW, nb);

    // CSR build (edges identical for both layers)
    k_zerodeg<<<(NN + 255) / 256, 256>>>();
    k_hist<<<(ETOT + 255) / 256, 256>>>(dstA);
    k_scan1<<<NB, SB>>>();
    k_scan2<<<1, 256>>>();
    k_scan3<<<(NN + 255) / 256, 256>>>();
    k_scat<<<(ETOT + 255) / 256, 256>>>(srcA, dstA);

    for (int l = 0; l < 2; l++) {
        int b = 8 + l * 6;
        const float* W  = (const float*)d_in[b];
        const float* as = (const float*)d_in[b + 1];
        const float* ad = (const float*)d_in[b + 2];
        const float* cb = (const float*)d_in[b + 3];
        const float* lg = (const float*)d_in[b + 4];
        const float* lb = (const float*)d_in[b + 5];

        k_va<<<8, 512>>>(W, as, ad);
        k_alpha<<<(NN * HH + 255) / 256, 256>>>();
        k_transform<<<NN / TNODES, 256, SMEM_T>>>(W);
        k_ex<<<(ETOT + 255) / 256, 256>>>();
        k_node<<<NN / 8, 256>>>(cb, lg, lb);
    }

    k_out<<<(NN * OO) / 256, 256>>>(oW, ob, (float*)d_out);
}

// round 3
// speedup vs baseline: 2.2108x; 1.0789x over previous
#include <cuda_runtime.h>
#include <cuda_fp16.h>

#define NN 100000
#define EE 1600000
#define ETOT (EE + NN)
#define GG 64
#define HH 4
#define CC 64
#define NF 32
#define DF 16
#define OO 32
#define HC (HH * CC)
#define SB 512
#define NB ((NN + SB - 1) / SB)   // 196

// ---------------- device scratch (static, allocation-free) ----------------
__device__ __align__(16) float  g_h[NN * CC];            // 25.6 MB
__device__ __align__(16) __half g_xh[NN * HC];           // 51.2 MB (fp16)
__device__ __align__(16) float  g_as[NN * HH];
__device__ __align__(16) float  g_ad[NN * HH];
__device__ __align__(16) float  g_dpre[GG * CC];
__device__ __align__(16) float  g_vas[HH * CC];
__device__ __align__(16) float  g_vad[HH * CC];
// CSR
__device__ int g_deg[NN];
__device__ int g_pref[NN];
__device__ int g_bsum[NB];
__device__ int g_boff[NB];
__device__ int g_rowstart[NN];
__device__ int g_cur[NN];
__device__ int g_csrc[ETOT];

// ---------------- helpers ----------------
__device__ __forceinline__ float lrelu(float v) { return v > 0.f ? v : 0.2f * v; }

typedef unsigned long long ull;
__device__ __forceinline__ ull pk2(float lo, float hi) {
    ull r; asm("mov.b64 %0, {%1, %2};" : "=l"(r) : "f"(lo), "f"(hi)); return r;
}
__device__ __forceinline__ ull fma2(ull a, ull b, ull c) {
    ull d; asm("fma.rn.f32x2 %0, %1, %2, %3;" : "=l"(d) : "l"(a), "l"(b), "l"(c)); return d;
}
__device__ __forceinline__ float2 upk2(ull v) {
    float2 f; asm("mov.b64 {%0, %1}, %2;" : "=f"(f.x), "=f"(f.y) : "l"(v)); return f;
}

// ---------------- init kernels ----------------
__global__ void k_dpre(const float* __restrict__ df, const float* __restrict__ dW,
                       const float* __restrict__ db) {
    int idx = blockIdx.x * blockDim.x + threadIdx.x;
    if (idx >= GG * CC) return;
    int g = idx / CC, c = idx % CC;
    const float4* a = (const float4*)(df + g * DF);
    const float4* w = (const float4*)(dW + c * DF);
    float acc = db[c];
#pragma unroll
    for (int i = 0; i < DF / 4; i++) {
        float4 av = a[i], wv = w[i];
        acc += av.x * wv.x + av.y * wv.y + av.z * wv.z + av.w * wv.w;
    }
    g_dpre[idx] = acc;
}

__global__ void k_hinit(const float* __restrict__ x, const int* __restrict__ batch,
                        const float* __restrict__ nW, const float* __restrict__ nb) {
    int idx = blockIdx.x * blockDim.x + threadIdx.x;
    if (idx >= NN * CC) return;
    int n = idx >> 6, c = idx & 63;
    float acc = nb[c] + g_dpre[batch[n] * CC + c];
    const float4* xr = (const float4*)(x + n * NF);
    const float4* wr = (const float4*)(nW + c * NF);
#pragma unroll
    for (int i = 0; i < NF / 4; i++) {
        float4 av = xr[i], wv = wr[i];
        acc += av.x * wv.x + av.y * wv.y + av.z * wv.z + av.w * wv.w;
    }
    g_h[idx] = acc;
}

// ---------------- CSR build (once per launch) ----------------
__global__ void k_zerodeg() {
    int i = blockIdx.x * blockDim.x + threadIdx.x;
    if (i < NN) g_deg[i] = 0;
}

__global__ void k_hist(const int* __restrict__ dst) {
    int e = blockIdx.x * blockDim.x + threadIdx.x;
    if (e >= ETOT) return;
    int d = (e < EE) ? dst[e] : e - EE;
    atomicAdd(&g_deg[d], 1);
}

__global__ void k_scan1() {
    __shared__ int sm[SB];
    int i = blockIdx.x * SB + threadIdx.x;
    int v = (i < NN) ? g_deg[i] : 0;
    sm[threadIdx.x] = v;
    __syncthreads();
    for (int o = 1; o < SB; o <<= 1) {
        int t = (threadIdx.x >= o) ? sm[threadIdx.x - o] : 0;
        __syncthreads();
        sm[threadIdx.x] += t;
        __syncthreads();
    }
    if (i < NN) g_pref[i] = sm[threadIdx.x];
    if (threadIdx.x == SB - 1) g_bsum[blockIdx.x] = sm[SB - 1];
}

__global__ void k_scan2() {
    __shared__ int sm[256];
    int t = threadIdx.x;
    sm[t] = (t < NB) ? g_bsum[t] : 0;
    __syncthreads();
    for (int o = 1; o < 256; o <<= 1) {
        int v = (t >= o) ? sm[t - o] : 0;
        __syncthreads();
        sm[t] += v;
        __syncthreads();
    }
    if (t < NB) g_boff[t] = (t == 0) ? 0 : sm[t - 1];
}

__global__ void k_scan3() {
    int i = blockIdx.x * blockDim.x + threadIdx.x;
    if (i >= NN) return;
    int start = g_pref[i] - g_deg[i] + g_boff[i / SB];
    g_rowstart[i] = start;
    g_cur[i] = start;
}

__global__ void k_scat(const int* __restrict__ src, const int* __restrict__ dst) {
    int e = blockIdx.x * blockDim.x + threadIdx.x;
    if (e >= ETOT) return;
    int s, d;
    if (e < EE) { s = src[e]; d = dst[e]; } else { s = e - EE; d = s; }
    int pos = atomicAdd(&g_cur[d], 1);
    g_csrc[pos] = s;
}

// ---------------- per-layer kernels ----------------
__global__ void k_va(const float* __restrict__ W, const float* __restrict__ asrc,
                     const float* __restrict__ adst) {
    int t = blockIdx.x * 512 + threadIdx.x;   // [0, 4096)
    int j = t >> 3;
    int part = t & 7;
    int which = j >> 8;
    int jj = j & 255;
    int h = jj >> 6, cp = jj & 63;
    const float* a = which ? adst : asrc;
    float acc = 0.f;
#pragma unroll
    for (int c = part * 8; c < part * 8 + 8; c++)
        acc += a[h * 64 + c] * W[(h * 64 + c) * 64 + cp];
#pragma unroll
    for (int o = 4; o; o >>= 1) acc += __shfl_xor_sync(0xffffffffu, acc, o);
    if (part == 0) (which ? g_vad : g_vas)[jj] = acc;
}

__global__ void k_alpha() {
    int idx = blockIdx.x * blockDim.x + threadIdx.x;
    if (idx >= NN * HH) return;
    int n = idx >> 2, h = idx & 3;
    const float4* hr = (const float4*)(g_h + n * CC);
    const float4* vs = (const float4*)(g_vas + h * CC);
    const float4* vd = (const float4*)(g_vad + h * CC);
    float s = 0.f, d = 0.f;
#pragma unroll
    for (int i = 0; i < CC / 4; i++) {
        float4 hv = hr[i], sv = vs[i], dv = vd[i];
        s += hv.x * sv.x + hv.y * sv.y + hv.z * sv.z + hv.w * sv.w;
        d += hv.x * dv.x + hv.y * dv.y + hv.z * dv.z + hv.w * dv.w;
    }
    g_as[idx] = s;
    g_ad[idx] = d;
}

// xh[n, k*64+jj] = sum_c h[n,c] * W[(k*64+jj)*64 + c]  -> fp16, f32x2 packed FMA
#define TNODES 32
#define W_STRIDE 260
#define H_STRIDE 36
#define SMEM_T ((64 * W_STRIDE + 64 * H_STRIDE) * 4)
__global__ void k_transform(const float* __restrict__ W) {
    extern __shared__ float sm[];
    float* Wsm = sm;                         // [c][jj*4+k], stride 260 per c
    float* Hsm = sm + 64 * W_STRIDE;         // [c][node], stride 36 per c
    int tid = threadIdx.x;
    int base = blockIdx.x * TNODES;

    for (int idx = tid; idx < 64 * 256; idx += 256) {
        int j = idx >> 6, c = idx & 63;      // coalesced read of W[j][c]
        int k = j >> 6, jj = j & 63;
        Wsm[c * W_STRIDE + jj * 4 + k] = W[idx];
    }
    for (int idx = tid; idx < TNODES * 64; idx += 256) {
        int n = idx >> 6, c = idx & 63;      // coalesced read of h
        Hsm[c * H_STRIDE + n] = g_h[(size_t)(base + n) * 64 + c];
    }
    __syncthreads();

    int jj = tid & 63;
    int grp = tid >> 6;                      // 0..3 -> nodes grp*8..grp*8+7
    ull a01[8], a23[8];
#pragma unroll
    for (int nd = 0; nd < 8; nd++) { a01[nd] = 0ull; a23[nd] = 0ull; }

#pragma unroll 2
    for (int c = 0; c < 64; c++) {
        float4 w = *(const float4*)(Wsm + c * W_STRIDE + jj * 4);
        ull w01 = pk2(w.x, w.y);
        ull w23 = pk2(w.z, w.w);
        float4 h0 = *(const float4*)(Hsm + c * H_STRIDE + grp * 8);
        float4 h1 = *(const float4*)(Hsm + c * H_STRIDE + grp * 8 + 4);
        ull hh;
        hh = pk2(h0.x, h0.x); a01[0] = fma2(w01, hh, a01[0]); a23[0] = fma2(w23, hh, a23[0]);
        hh = pk2(h0.y, h0.y); a01[1] = fma2(w01, hh, a01[1]); a23[1] = fma2(w23, hh, a23[1]);
        hh = pk2(h0.z, h0.z); a01[2] = fma2(w01, hh, a01[2]); a23[2] = fma2(w23, hh, a23[2]);
        hh = pk2(h0.w, h0.w); a01[3] = fma2(w01, hh, a01[3]); a23[3] = fma2(w23, hh, a23[3]);
        hh = pk2(h1.x, h1.x); a01[4] = fma2(w01, hh, a01[4]); a23[4] = fma2(w23, hh, a23[4]);
        hh = pk2(h1.y, h1.y); a01[5] = fma2(w01, hh, a01[5]); a23[5] = fma2(w23, hh, a23[5]);
        hh = pk2(h1.z, h1.z); a01[6] = fma2(w01, hh, a01[6]); a23[6] = fma2(w23, hh, a23[6]);
        hh = pk2(h1.w, h1.w); a01[7] = fma2(w01, hh, a01[7]); a23[7] = fma2(w23, hh, a23[7]);
    }

#pragma unroll
    for (int nd = 0; nd < 8; nd++) {
        int n = base + grp * 8 + nd;
        __half* xr = g_xh + (size_t)n * 256;
        float2 f01 = upk2(a01[nd]);
        float2 f23 = upk2(a23[nd]);
        xr[jj]       = __float2half(f01.x);
        xr[64 + jj]  = __float2half(f01.y);
        xr[128 + jj] = __float2half(f23.x);
        xr[192 + jj] = __float2half(f23.y);
    }
}

// fused: per-edge exp (inline) + gather-aggregate + softmax normalize +
// head-mean + LN + ReLU + residual.  one warp per destination node.
__global__ void k_node(const float* __restrict__ cb, const float* __restrict__ lg,
                       const float* __restrict__ lb) {
    __shared__ float se[8][32][4];
    int warp = threadIdx.x >> 5, lane = threadIdx.x & 31;
    int n = blockIdx.x * 8 + warp;           // grid exact: NN/8
    int row = g_rowstart[n];
    int deg = g_deg[n];
    int my_h = lane >> 3;
    int cbase = (lane & 7) * 8;
    float4 ad4 = *(const float4*)(g_ad + (size_t)n * 4);

    float acc[8];
#pragma unroll
    for (int k = 0; k < 8; k++) acc[k] = 0.f;
    float4 sum4 = make_float4(0.f, 0.f, 0.f, 0.f);

    for (int base = 0; base < deg; base += 32) {
        int i = base + lane;
        int s_l = 0;
        if (i < deg) {
            s_l = __ldg(g_csrc + row + i);
            float4 a4 = *(const float4*)(g_as + (size_t)s_l * 4);
            float4 e4;
            e4.x = __expf(lrelu(a4.x + ad4.x));
            e4.y = __expf(lrelu(a4.y + ad4.y));
            e4.z = __expf(lrelu(a4.z + ad4.z));
            e4.w = __expf(lrelu(a4.w + ad4.w));
            sum4.x += e4.x; sum4.y += e4.y; sum4.z += e4.z; sum4.w += e4.w;
            *(float4*)&se[warp][lane][0] = e4;
        }
        __syncwarp();
        int cnt = min(32, deg - base);
#pragma unroll 4
        for (int k = 0; k < cnt; k++) {
            int s = __shfl_sync(0xffffffffu, s_l, k);
            float a = se[warp][k][my_h];
            uint4 raw = __ldg((const uint4*)(g_xh + (size_t)s * 256 + lane * 8));
            float2 f0 = __half22float2(*reinterpret_cast<__half2*>(&raw.x));
            float2 f1 = __half22float2(*reinterpret_cast<__half2*>(&raw.y));
            float2 f2 = __half22float2(*reinterpret_cast<__half2*>(&raw.z));
            float2 f3 = __half22float2(*reinterpret_cast<__half2*>(&raw.w));
            acc[0] = fmaf(a, f0.x, acc[0]); acc[1] = fmaf(a, f0.y, acc[1]);
            acc[2] = fmaf(a, f1.x, acc[2]); acc[3] = fmaf(a, f1.y, acc[3]);
            acc[4] = fmaf(a, f2.x, acc[4]); acc[5] = fmaf(a, f2.y, acc[5]);
            acc[6] = fmaf(a, f3.x, acc[6]); acc[7] = fmaf(a, f3.y, acc[7]);
        }
        __syncwarp();
    }

    // warp-reduce per-head exp sums
#pragma unroll
    for (int o = 16; o; o >>= 1) {
        sum4.x += __shfl_xor_sync(0xffffffffu, sum4.x, o);
        sum4.y += __shfl_xor_sync(0xffffffffu, sum4.y, o);
        sum4.z += __shfl_xor_sync(0xffffffffu, sum4.z, o);
        sum4.w += __shfl_xor_sync(0xffffffffu, sum4.w, o);
    }
    float sh = (my_h == 0) ? sum4.x : (my_h == 1) ? sum4.y : (my_h == 2) ? sum4.z : sum4.w;
    float rr = 1.0f / (sh + 1e-16f);
#pragma unroll
    for (int k = 0; k < 8; k++) acc[k] *= rr;

    // sum across heads
#pragma unroll
    for (int k = 0; k < 8; k++) {
        acc[k] += __shfl_xor_sync(0xffffffffu, acc[k], 8);
        acc[k] += __shfl_xor_sync(0xffffffffu, acc[k], 16);
    }

    // head mean + bias, LN over 64 channels
    float v[8], psum = 0.f, psq = 0.f;
#pragma unroll
    for (int k = 0; k < 8; k++) {
        v[k] = 0.25f * acc[k] + cb[cbase + k];
        psum += v[k];
        psq += v[k] * v[k];
    }
#pragma unroll
    for (int o = 4; o; o >>= 1) {
        psum += __shfl_xor_sync(0xffffffffu, psum, o);
        psq  += __shfl_xor_sync(0xffffffffu, psq, o);
    }
    float mu = psum * (1.f / 64.f);
    float var = psq * (1.f / 64.f) - mu * mu;
    float rs = rsqrtf(var + 1e-5f);

    if (lane < 8) {
        float* hp = g_h + (size_t)n * 64 + cbase;
        float4 o0 = *(float4*)hp;
        float4 o1 = *(float4*)(hp + 4);
        float y;
        y = (v[0] - mu) * rs * lg[cbase + 0] + lb[cbase + 0]; o0.x += fmaxf(y, 0.f);
        y = (v[1] - mu) * rs * lg[cbase + 1] + lb[cbase + 1]; o0.y += fmaxf(y, 0.f);
        y = (v[2] - mu) * rs * lg[cbase + 2] + lb[cbase + 2]; o0.z += fmaxf(y, 0.f);
        y = (v[3] - mu) * rs * lg[cbase + 3] + lb[cbase + 3]; o0.w += fmaxf(y, 0.f);
        y = (v[4] - mu) * rs * lg[cbase + 4] + lb[cbase + 4]; o1.x += fmaxf(y, 0.f);
        y = (v[5] - mu) * rs * lg[cbase + 5] + lb[cbase + 5]; o1.y += fmaxf(y, 0.f);
        y = (v[6] - mu) * rs * lg[cbase + 6] + lb[cbase + 6]; o1.z += fmaxf(y, 0.f);
        y = (v[7] - mu) * rs * lg[cbase + 7] + lb[cbase + 7]; o1.w += fmaxf(y, 0.f);
        *(float4*)hp = o0;
        *(float4*)(hp + 4) = o1;
    }
}

__global__ void k_out(const float* __restrict__ oW, const float* __restrict__ ob,
                      float* __restrict__ out) {
    int idx = blockIdx.x * blockDim.x + threadIdx.x;
    if (idx >= NN * OO) return;
    int n = idx >> 5, o = idx & 31;
    const float4* hr = (const float4*)(g_h + n * 64);
    const float4* wr = (const float4*)(oW + o * 64);
    float acc = ob[o];
#pragma unroll
    for (int i = 0; i < 16; i++) {
        float4 hv = hr[i], wv = wr[i];
        acc += hv.x * wv.x + hv.y * wv.y + hv.z * wv.z + hv.w * wv.w;
    }
    out[idx] = acc;
}

// ---------------- launch ----------------
extern "C" void kernel_launch(void* const* d_in, const int* in_sizes, int n_in,
                              void* d_out, int out_size) {
    const float* x = (const float*)d_in[0];
    const int* eidx;
    const float* dfeat;
    if (in_sizes[1] == GG * DF) { dfeat = (const float*)d_in[1]; eidx = (const int*)d_in[2]; }
    else                        { eidx = (const int*)d_in[1];    dfeat = (const float*)d_in[2]; }
    const int*   batch = (const int*)d_in[3];
    const float* nW = (const float*)d_in[4];
    const float* nb = (const float*)d_in[5];
    const float* dW = (const float*)d_in[6];
    const float* db = (const float*)d_in[7];
    const float* oW = (const float*)d_in[20];
    const float* ob = (const float*)d_in[21];
    const int* srcA = eidx;
    const int* dstA = eidx + EE;

    cudaFuncSetAttribute(k_transform, cudaFuncAttributeMaxDynamicSharedMemorySize, SMEM_T);

    k_dpre<<<(GG * CC + 255) / 256, 256>>>(dfeat, dW, db);
    k_hinit<<<(NN * CC) / 256, 256>>>(x, batch, nW, nb);

    // CSR build (edges identical for both layers)
    k_zerodeg<<<(NN + 255) / 256, 256>>>();
    k_hist<<<(ETOT + 255) / 256, 256>>>(dstA);
    k_scan1<<<NB, SB>>>();
    k_scan2<<<1, 256>>>();
    k_scan3<<<(NN + 255) / 256, 256>>>();
    k_scat<<<(ETOT + 255) / 256, 256>>>(srcA, dstA);

    for (int l = 0; l < 2; l++) {
        int b = 8 + l * 6;
        const float* W  = (const float*)d_in[b];
        const float* as = (const float*)d_in[b + 1];
        const float* ad = (const float*)d_in[b + 2];
        const float* cb = (const float*)d_in[b + 3];
        const float* lg = (const float*)d_in[b + 4];
        const float* lb = (const float*)d_in[b + 5];

        k_va<<<8, 512>>>(W, as, ad);
        k_alpha<<<(NN * HH + 255) / 256, 256>>>();
        k_transform<<<NN / TNODES, 256, SMEM_T>>>(W);
        k_node<<<NN / 8, 256>>>(cb, lg, lb);
    }

    k_out<<<(NN * OO) / 256, 256>>>(oW, ob, (float*)d_out);
}